// round 3
// baseline (speedup 1.0000x reference)
#include <cuda_runtime.h>
#include <cuda_bf16.h>
#include <cub/cub.cuh>

#define NROWS 260000
#define NCLS  1024
#define NBINS 20
#define BINSZ 13000
#define TEMP_CAP (1u << 25)  /* 32 MB scratch for CUB radix sort */

// ---- static device scratch (no allocations allowed) ----
__device__ unsigned int g_keys[NROWS];   // conf float bits (positive -> uint order == float order)
__device__ unsigned int g_vals[NROWS];   // accuracy 0/1
__device__ unsigned int g_keys2[NROWS];  // sorted keys
__device__ unsigned int g_vals2[NROWS];  // sorted accs
__device__ float        g_ce[NBINS];
__device__ int          g_is64;
__device__ __align__(256) unsigned char g_temp[TEMP_CAP];

// Detect whether labels buffer is int64 (odd 32-bit words all zero) or int32.
// Deterministic: depends only on input data. P(false positive | int32) = (1/1024)^32.
__global__ void detect_kernel(const int* __restrict__ labels32) {
    unsigned mask = __ballot_sync(0xffffffffu, labels32[2 * threadIdx.x + 1] == 0);
    if (threadIdx.x == 0) g_is64 = (mask == 0xffffffffu) ? 1 : 0;
}

// One block per row: max + first-occurrence argmax + sum(exp(x - max)).
// conf = 1/sumexp  (== max of softmax row).
__global__ void __launch_bounds__(256) row_kernel(const float* __restrict__ logits,
                                                  const void* __restrict__ labels) {
    const int row = blockIdx.x;
    const int t = threadIdx.x;
    const float4 v = reinterpret_cast<const float4*>(logits)[(size_t)row * (NCLS / 4) + t];

    // local max / first-index argmax over 4
    float m = v.x; int mi = 4 * t;
    if (v.y > m) { m = v.y; mi = 4 * t + 1; }
    if (v.z > m) { m = v.z; mi = 4 * t + 2; }
    if (v.w > m) { m = v.w; mi = 4 * t + 3; }

    // warp reduce (max, min-index tiebreak)
    #pragma unroll
    for (int o = 16; o > 0; o >>= 1) {
        float om = __shfl_down_sync(0xffffffffu, m, o);
        int   oi = __shfl_down_sync(0xffffffffu, mi, o);
        if (om > m || (om == m && oi < mi)) { m = om; mi = oi; }
    }

    __shared__ float sm[8];
    __shared__ int   si[8];
    __shared__ float se[8];
    const int warp = t >> 5, lane = t & 31;
    if (lane == 0) { sm[warp] = m; si[warp] = mi; }
    __syncthreads();

    if (warp == 0) {
        m  = (lane < 8) ? sm[lane] : -3.402823466e38f;
        mi = (lane < 8) ? si[lane] : 0x7fffffff;
        #pragma unroll
        for (int o = 4; o > 0; o >>= 1) {
            float om = __shfl_down_sync(0xffffffffu, m, o);
            int   oi = __shfl_down_sync(0xffffffffu, mi, o);
            if (om > m || (om == m && oi < mi)) { m = om; mi = oi; }
        }
        if (lane == 0) { sm[0] = m; si[0] = mi; }
    }
    __syncthreads();

    const float M = sm[0];
    float e = __expf(v.x - M) + __expf(v.y - M) + __expf(v.z - M) + __expf(v.w - M);
    #pragma unroll
    for (int o = 16; o > 0; o >>= 1) e += __shfl_down_sync(0xffffffffu, e, o);
    if (lane == 0) se[warp] = e;
    __syncthreads();

    if (t == 0) {
        float s = se[0] + se[1] + se[2] + se[3] + se[4] + se[5] + se[6] + se[7];
        float conf = 1.0f / s;  // == exp(max - lse) == max softmax
        g_keys[row] = __float_as_uint(conf);
        int lab = g_is64 ? (int)((const long long*)labels)[row]
                         : ((const int*)labels)[row];
        g_vals[row] = (si[0] == lab) ? 1u : 0u;
    }
}

// 20 blocks: bin b covers sorted ranks [b*13000, (b+1)*13000)
__global__ void __launch_bounds__(256) bin_kernel() {
    const int b = blockIdx.x, t = threadIdx.x;
    const unsigned int* k = g_keys2 + b * BINSZ;
    const unsigned int* a = g_vals2 + b * BINSZ;
    float sc = 0.0f, sa = 0.0f;
    for (int i = t; i < BINSZ; i += 256) {
        sc += __uint_as_float(k[i]);
        sa += (float)a[i];
    }
    #pragma unroll
    for (int o = 16; o > 0; o >>= 1) {
        sc += __shfl_down_sync(0xffffffffu, sc, o);
        sa += __shfl_down_sync(0xffffffffu, sa, o);
    }
    __shared__ float ssc[8], ssa[8];
    const int warp = t >> 5, lane = t & 31;
    if (lane == 0) { ssc[warp] = sc; ssa[warp] = sa; }
    __syncthreads();
    if (t == 0) {
        float c = 0.0f, aa = 0.0f;
        #pragma unroll
        for (int w = 0; w < 8; w++) { c += ssc[w]; aa += ssa[w]; }
        g_ce[b] = fabsf(c - aa) / (float)BINSZ;
    }
}

__global__ void final_kernel(float* __restrict__ out) {
    const int t = threadIdx.x;
    float v  = (t < NBINS) ? g_ce[t] : 0.0f;
    float mv = (t < NBINS) ? g_ce[t] : -1.0f;
    #pragma unroll
    for (int o = 16; o > 0; o >>= 1) {
        v += __shfl_down_sync(0xffffffffu, v, o);
        float om = __shfl_down_sync(0xffffffffu, mv, o);
        mv = fmaxf(mv, om);
    }
    if (t == 0) {
        out[0] = v / (float)NBINS;  // ece
        out[1] = mv;                // mce
    }
}

extern "C" void kernel_launch(void* const* d_in, const int* in_sizes, int n_in,
                              void* d_out, int out_size) {
    const float* logits = (const float*)d_in[0];
    const void*  labels = d_in[1];
    float* out = (float*)d_out;

    unsigned int *kin, *vin, *kout, *vout;
    float* ce_ptr;
    void* temp;
    cudaGetSymbolAddress((void**)&kin,  g_keys);
    cudaGetSymbolAddress((void**)&vin,  g_vals);
    cudaGetSymbolAddress((void**)&kout, g_keys2);
    cudaGetSymbolAddress((void**)&vout, g_vals2);
    cudaGetSymbolAddress((void**)&ce_ptr, g_ce);
    cudaGetSymbolAddress(&temp, g_temp);
    (void)ce_ptr;

    detect_kernel<<<1, 32>>>((const int*)labels);
    row_kernel<<<NROWS, 256>>>(logits, labels);

    // Stable radix sort (matches jnp.argsort stable tie-breaking by index).
    size_t temp_bytes = (size_t)TEMP_CAP;
    cub::DeviceRadixSort::SortPairs(temp, temp_bytes,
                                    kin, kout, vin, vout,
                                    NROWS, 0, 32, (cudaStream_t)0);

    bin_kernel<<<NBINS, 256>>>();
    final_kernel<<<1, 32>>>(out);
}

// round 5
// speedup vs baseline: 2.0347x; 2.0347x over previous
#include <cuda_runtime.h>
#include <cuda_bf16.h>
#include <cub/cub.cuh>
#include <float.h>

#define NROWS 260000
#define NCLS  1024
#define NBINS 20
#define BINSZ 13000
#define TEMP_CAP (1u << 25)  /* 32 MB scratch for CUB radix sort */

// ---- static device scratch (no allocations allowed) ----
__device__ unsigned int g_keys[NROWS];   // conf float bits (positive -> uint order == float order)
__device__ unsigned int g_vals[NROWS];   // accuracy 0/1
__device__ unsigned int g_keys2[NROWS];  // sorted keys
__device__ unsigned int g_vals2[NROWS];  // sorted accs
__device__ float        g_ce[NBINS];
__device__ int          g_is64;
__device__ __align__(256) unsigned char g_temp[TEMP_CAP];

// Detect whether labels buffer is int64 (odd 32-bit words all zero) or int32.
// Deterministic: depends only on input data. P(false positive | int32) = (1/1024)^32.
__global__ void detect_kernel(const int* __restrict__ labels32) {
    unsigned mask = __ballot_sync(0xffffffffu, labels32[2 * threadIdx.x + 1] == 0);
    if (threadIdx.x == 0) g_is64 = (mask == 0xffffffffu) ? 1 : 0;
}

// Warp-per-row: each lane front-batches 8x LDG.128 (128B/lane, MLP_p1=8).
// Pure warp-shuffle reductions: no smem, no __syncthreads.
// conf = 1/sum(exp(x-max)) == max of softmax row. argmax = first occurrence.
__global__ void __launch_bounds__(256) row_kernel(const float* __restrict__ logits,
                                                  const void* __restrict__ labels) {
    const int warp = threadIdx.x >> 5;
    const int lane = threadIdx.x & 31;
    const int row  = blockIdx.x * 8 + warp;

    const float4* base = reinterpret_cast<const float4*>(logits) + (size_t)row * (NCLS / 4);
    float4 v[8];
    #pragma unroll
    for (int i = 0; i < 8; i++) v[i] = __ldcs(&base[i * 32 + lane]);

    // local max + first-occurrence argmax (per-lane indices increase with i)
    float m = -FLT_MAX; int mi = 0x7fffffff;
    #pragma unroll
    for (int i = 0; i < 8; i++) {
        const int b = (i * 32 + lane) * 4;
        if (v[i].x > m) { m = v[i].x; mi = b;     }
        if (v[i].y > m) { m = v[i].y; mi = b + 1; }
        if (v[i].z > m) { m = v[i].z; mi = b + 2; }
        if (v[i].w > m) { m = v[i].w; mi = b + 3; }
    }
    // butterfly reduce: max with min-index tiebreak (== jnp.argmax first occurrence)
    #pragma unroll
    for (int o = 16; o > 0; o >>= 1) {
        float om = __shfl_xor_sync(0xffffffffu, m,  o);
        int   oi = __shfl_xor_sync(0xffffffffu, mi, o);
        if (om > m || (om == m && oi < mi)) { m = om; mi = oi; }
    }

    float e = 0.0f;
    #pragma unroll
    for (int i = 0; i < 8; i++) {
        e += __expf(v[i].x - m) + __expf(v[i].y - m)
           + __expf(v[i].z - m) + __expf(v[i].w - m);
    }
    #pragma unroll
    for (int o = 16; o > 0; o >>= 1) e += __shfl_xor_sync(0xffffffffu, e, o);

    if (lane == 0) {
        const float conf = 1.0f / e;   // == exp(max - logsumexp) == max softmax
        g_keys[row] = __float_as_uint(conf);
        const int lab = g_is64 ? (int)((const long long*)labels)[row]
                               : ((const int*)labels)[row];
        g_vals[row] = (mi == lab) ? 1u : 0u;
    }
}

// 20 blocks: bin b covers sorted ranks [b*13000, (b+1)*13000)
__global__ void __launch_bounds__(256) bin_kernel() {
    const int b = blockIdx.x, t = threadIdx.x;
    const unsigned int* k = g_keys2 + b * BINSZ;
    const unsigned int* a = g_vals2 + b * BINSZ;
    float sc = 0.0f, sa = 0.0f;
    for (int i = t; i < BINSZ; i += 256) {
        sc += __uint_as_float(k[i]);
        sa += (float)a[i];
    }
    #pragma unroll
    for (int o = 16; o > 0; o >>= 1) {
        sc += __shfl_down_sync(0xffffffffu, sc, o);
        sa += __shfl_down_sync(0xffffffffu, sa, o);
    }
    __shared__ float ssc[8], ssa[8];
    const int warp = t >> 5, lane = t & 31;
    if (lane == 0) { ssc[warp] = sc; ssa[warp] = sa; }
    __syncthreads();
    if (t == 0) {
        float c = 0.0f, aa = 0.0f;
        #pragma unroll
        for (int w = 0; w < 8; w++) { c += ssc[w]; aa += ssa[w]; }
        g_ce[b] = fabsf(c - aa) / (float)BINSZ;
    }
}

__global__ void final_kernel(float* __restrict__ out) {
    const int t = threadIdx.x;
    float v  = (t < NBINS) ? g_ce[t] : 0.0f;
    float mv = (t < NBINS) ? g_ce[t] : -1.0f;
    #pragma unroll
    for (int o = 16; o > 0; o >>= 1) {
        v += __shfl_down_sync(0xffffffffu, v, o);
        float om = __shfl_down_sync(0xffffffffu, mv, o);
        mv = fmaxf(mv, om);
    }
    if (t == 0) {
        out[0] = v / (float)NBINS;  // ece
        out[1] = mv;                // mce
    }
}

extern "C" void kernel_launch(void* const* d_in, const int* in_sizes, int n_in,
                              void* d_out, int out_size) {
    const float* logits = (const float*)d_in[0];
    const void*  labels = d_in[1];
    float* out = (float*)d_out;

    unsigned int *kin, *vin, *kout, *vout;
    void* temp;
    cudaGetSymbolAddress((void**)&kin,  g_keys);
    cudaGetSymbolAddress((void**)&vin,  g_vals);
    cudaGetSymbolAddress((void**)&kout, g_keys2);
    cudaGetSymbolAddress((void**)&vout, g_vals2);
    cudaGetSymbolAddress(&temp, g_temp);

    detect_kernel<<<1, 32>>>((const int*)labels);
    row_kernel<<<NROWS / 8, 256>>>(logits, labels);

    // Stable radix sort (matches jnp.argsort stable tie-breaking by index).
    size_t temp_bytes = (size_t)TEMP_CAP;
    cub::DeviceRadixSort::SortPairs(temp, temp_bytes,
                                    kin, kout, vin, vout,
                                    NROWS, 0, 32, (cudaStream_t)0);

    bin_kernel<<<NBINS, 256>>>();
    final_kernel<<<1, 32>>>(out);
}